// round 12
// baseline (speedup 1.0000x reference)
#include <cuda_runtime.h>
#include <cuda_fp16.h>
#include <cstdint>

// Problem constants
#define BB 32
#define NN 8192
#define GG 128
#define MM 8320            // N + G
#define KOUT 512
#define MAXFG 128

#define NBIN_NEG 512
#define NBIN_POS 256
#define NBINS 768          // neg bins [0,512), pos bins [512,768)
#define BCAP 64            // bucket capacity (expected load ~16)

#define CHUNKS 37          // per-batch chunks in k_iou (32*37 = 1184 = 8*148 blocks)
#define CHUNK 225          // ceil(8320/37); 128 threads x up to 2 boxes

#define SORT_SLICES 8
#define SORT_WARPS 24      // 768 threads
#define SORT_STRIDE (SORT_SLICES * SORT_WARPS)   // 192 warps per batch

// f16 screen margin: worst-case abs error of the half2 pipeline is <= 0.011
#define EPS16 0.02f

typedef unsigned long long u64;

// Scratch (no allocations allowed). g_hist is zero at load; k_emit re-zeroes.
__device__ int g_hist[BB * NBINS];
__device__ u64 g_bucket[BB * NBINS * BCAP];
__device__ u64 g_sorted[BB * 896];
__device__ int g_meta[BB * 4];

__device__ __forceinline__ unsigned int fkey(float f) {
    unsigned int u = __float_as_uint(f);
    return (u & 0x80000000u) ? ~u : (u | 0x80000000u);
}

// Monotone fine binning of the key's high word.
__device__ __forceinline__ int binof(unsigned hi) {
    if (hi < 0x80000000u) return -1;
    float c = __uint_as_float(hi ^ 0x80000000u);
    if (hi >= 0xC0000000u) {
        int t = (int)((c - 2.0f) * (float)NBIN_POS);
        return NBIN_NEG + (t > NBIN_POS - 1 ? NBIN_POS - 1 : t);
    }
    int t = (int)(c * (float)NBIN_NEG);
    return t > NBIN_NEG - 1 ? NBIN_NEG - 1 : t;
}

__device__ __forceinline__ void emit_key(int b, int m, bool pos, bool neg, float nv) {
    float c = pos ? (2.0f + nv) : (neg ? nv : -1.0f);
    unsigned hi = fkey(c);
    u64 key = ((u64)hi << 32) | (u64)(0xFFFFFFFFu - (unsigned)m);
    int bin = binof(hi);
    if (bin >= 0) {
        int slot = atomicAdd(&g_hist[b * NBINS + bin], 1);
        if (slot < BCAP)
            g_bucket[(size_t)(b * NBINS + bin) * BCAP + slot] = key;
    }
}

__device__ __forceinline__ __half2 h2bc(unsigned u) {
    return *reinterpret_cast<__half2*>(&u);
}
__device__ __forceinline__ unsigned bch2(__half2 h) {
    return *reinterpret_cast<unsigned*>(&h);
}

// ---------------------------------------------------------------------------
// K1: fp16x2 screen (2 gts/instr, 2 boxes/thread) + exact fp32 recheck for
// boxes with |margin| <= EPS16. grid = 1184 blocks x 128 threads.
// ---------------------------------------------------------------------------
__global__ __launch_bounds__(128) void k_iou(
    const float4* __restrict__ boxes,   // [B][N]  (ymin,xmin,ymax,xmax)
    const float4* __restrict__ gts,     // [B][G]
    const float*  __restrict__ noise)   // [B][M]
{
    __shared__ float4 sgf[GG];      // f32 {gz, -gx, gw, -gy}  (exact recheck)
    __shared__ float  sngaf[GG];    // f32 -ga
    __shared__ float4 sh2[GG / 2];  // half2x4 {zz, xx, ww, yy} for gt pair
    __shared__ unsigned snga2[GG / 2];
    __shared__ int sq[256];
    __shared__ int sqc;
    const int b     = blockIdx.x / CHUNKS;
    const int chunk = blockIdx.x % CHUNKS;
    const int tid   = threadIdx.x;

    if (tid == 0) sqc = 0;
    {
        float4 g = gts[b * GG + tid];
        float ga = (g.z - g.x) * (g.w - g.y);
        sgf[tid] = make_float4(g.z, -g.x, g.w, -g.y);
        sngaf[tid] = -ga;
    }
    __syncthreads();
    if (tid < GG / 2) {
        float4 a = sgf[2 * tid], c = sgf[2 * tid + 1];
        float4 p;
        p.x = __uint_as_float(bch2(__floats2half2_rn(a.x, c.x)));   // gz pair
        p.y = __uint_as_float(bch2(__floats2half2_rn(a.y, c.y)));   // -gx pair
        p.z = __uint_as_float(bch2(__floats2half2_rn(a.z, c.z)));   // gw pair
        p.w = __uint_as_float(bch2(__floats2half2_rn(a.w, c.w)));   // -gy pair
        sh2[tid] = p;
        snga2[tid] = bch2(__floats2half2_rn(sngaf[2 * tid], sngaf[2 * tid + 1]));
    }
    __syncthreads();

    const int mstart = chunk * CHUNK;
    const int mend   = (mstart + CHUNK < MM) ? (mstart + CHUNK) : MM;
    const int mA = mstart + tid;
    const int mB = mA + 128;
    const bool vA = mA < mend;
    const bool vB = mB < mend;

    if (vA) {
        float4 bxA = (mA < NN) ? boxes[b * NN + mA] : gts[b * GG + (mA - NN)];
        float4 bxB = vB ? ((mB < NN) ? boxes[b * NN + mB] : gts[b * GG + (mB - NN)]) : bxA;
        float nvA = noise[b * MM + mA];
        float nvB = vB ? noise[b * MM + mB] : 0.0f;
        float baA = (bxA.z - bxA.x) * (bxA.w - bxA.y);
        float baB = (bxB.z - bxB.x) * (bxB.w - bxB.y);

        const __half2 zA2  = __float2half2_rn(bxA.z);
        const __half2 nxA2 = __float2half2_rn(-bxA.x);
        const __half2 wA2  = __float2half2_rn(bxA.w);
        const __half2 nyA2 = __float2half2_rn(-bxA.y);
        const __half2 zB2  = __float2half2_rn(bxB.z);
        const __half2 nxB2 = __float2half2_rn(-bxB.x);
        const __half2 wB2  = __float2half2_rn(bxB.w);
        const __half2 nyB2 = __float2half2_rn(-bxB.y);
        const __half2 zero2  = __float2half2_rn(0.0f);
        const __half2 three2 = __float2half2_rn(3.0f);
        __half2 dmA = __float2half2_rn(-30000.0f);
        __half2 dmB = dmA;

        #pragma unroll 4
        for (int i = 0; i < GG / 2; i++) {
            float4 p = sh2[i];
            __half2 gz  = h2bc(__float_as_uint(p.x));
            __half2 ngx = h2bc(__float_as_uint(p.y));
            __half2 gw  = h2bc(__float_as_uint(p.z));
            __half2 ngy = h2bc(__float_as_uint(p.w));
            __half2 nga = h2bc(snga2[i]);
            {
                __half2 ih = __hadd2(__hmin2(zA2, gz), __hmin2(nxA2, ngx));
                __half2 iw = __hadd2(__hmin2(wA2, gw), __hmin2(nyA2, ngy));
                __half2 ia = __hmul2(__hmax2(ih, zero2), iw);  // one-sided clamp
                dmA = __hmax2(dmA, __hfma2(three2, ia, nga));
            }
            {
                __half2 ih = __hadd2(__hmin2(zB2, gz), __hmin2(nxB2, ngx));
                __half2 iw = __hadd2(__hmin2(wB2, gw), __hmin2(nyB2, ngy));
                __half2 ia = __hmul2(__hmax2(ih, zero2), iw);
                dmB = __hmax2(dmB, __hfma2(three2, ia, nga));
            }
        }

        float dA = fmaxf(__low2float(dmA), __high2float(dmA));
        float dB = fmaxf(__low2float(dmB), __high2float(dmB));
        float gA = dA - baA;
        float gB = dB - baB;

        if (gA > EPS16)       emit_key(b, mA, true, false, nvA);
        else if (gA < -EPS16) emit_key(b, mA, false, true, nvA);
        else                  sq[atomicAdd(&sqc, 1)] = mA;

        if (vB) {
            if (gB > EPS16)       emit_key(b, mB, true, false, nvB);
            else if (gB < -EPS16) emit_key(b, mB, false, true, nvB);
            else                  sq[atomicAdd(&sqc, 1)] = mB;
        }
    }
    __syncthreads();

    // Exact fp32 recheck (R10-identical arithmetic) for ambiguous boxes.
    const int qc = sqc;
    for (int qi = tid; qi < qc; qi += 128) {
        int m = sq[qi];
        float4 bx = (m < NN) ? boxes[b * NN + m] : gts[b * GG + (m - NN)];
        float ba = (bx.z - bx.x) * (bx.w - bx.y);
        float nv = noise[b * MM + m];
        const float z = bx.z, nx = -bx.x, w = bx.w, ny = -bx.y;
        float u = -1e30f;
        #pragma unroll 4
        for (int g = 0; g < GG; g++) {
            float4 G = sgf[g];
            float nga = sngaf[g];
            float ih = fminf(z, G.x) + fminf(nx, G.y);
            float iw = fminf(w, G.z) + fminf(ny, G.w);
            float ia = fmaxf(ih, 0.f) * fmaxf(iw, 0.f);
            u = fmaxf(u, fmaf(3.0f, ia, nga));
        }
        emit_key(b, m, u > ba, u < ba, nv);
    }
}

// Warp-level bitonic sort, descending, 32 elems (1 per lane).
__device__ __forceinline__ void warp_sort32(u64& v) {
    const int lane = threadIdx.x & 31;
    #pragma unroll
    for (unsigned k = 2; k <= 32; k <<= 1) {
        #pragma unroll
        for (unsigned j = k >> 1; j >= 1; j >>= 1) {
            u64 o = __shfl_xor_sync(0xFFFFFFFFu, v, j);
            bool desc = (lane & k) == 0;
            bool up   = (lane & j) == 0;
            bool keepmax = (up == desc);
            v = keepmax ? (v > o ? v : o) : (v < o ? v : o);
        }
    }
}

// Warp-level bitonic sort, descending, 64 elems (2 per lane: e = 2*lane+s).
__device__ __forceinline__ void warp_sort64(u64& v0, u64& v1) {
    const int lane = threadIdx.x & 31;
    #pragma unroll
    for (unsigned k = 2; k <= 64; k <<= 1) {
        #pragma unroll
        for (unsigned j = k >> 1; j >= 1; j >>= 1) {
            bool desc = (((unsigned)(lane << 1)) & k) == 0;
            if (j == 1) {
                u64 hi2 = v0 > v1 ? v0 : v1;
                u64 lo2 = v0 > v1 ? v1 : v0;
                v0 = desc ? hi2 : lo2;
                v1 = desc ? lo2 : hi2;
            } else {
                unsigned lm = j >> 1;
                u64 o0 = __shfl_xor_sync(0xFFFFFFFFu, v0, lm);
                u64 o1 = __shfl_xor_sync(0xFFFFFFFFu, v1, lm);
                bool up = (lane & lm) == 0;
                bool keepmax = (up == desc);
                v0 = keepmax ? (v0 > o0 ? v0 : o0) : (v0 < o0 ? v0 : o0);
                v1 = keepmax ? (v1 > o1 ? v1 : o1) : (v1 < o1 ? v1 : o1);
            }
        }
    }
}

// ---------------------------------------------------------------------------
// K2a: parallel counting-sort. grid (BB, 8) x 768 threads (no clusters).
// ---------------------------------------------------------------------------
__global__ __launch_bounds__(768) void k_sort(void) {
    __shared__ int h[NBINS];
    __shared__ int suf[NBINS];
    __shared__ int s_tpos, s_tneg;
    const int b = blockIdx.x;
    const int slice = blockIdx.y;
    const int tid = threadIdx.x;
    const int lane = tid & 31;
    const int warp = tid >> 5;

    if (tid < NBINS) {
        int v = g_hist[b * NBINS + tid];
        if (v > BCAP) v = BCAP;
        h[tid] = v;
        suf[tid] = v;
    }
    if (tid == 0) { s_tpos = NBIN_NEG; s_tneg = 0; }
    __syncthreads();

    // Region-masked suffix scan (neg [0,512), pos [512,768))
    #pragma unroll
    for (int d = 1; d < NBIN_NEG; d <<= 1) {
        int add = 0;
        if (tid < NBINS) {
            int e = (tid < NBIN_NEG) ? NBIN_NEG : NBINS;
            if (tid + d < e) add = suf[tid + d];
        }
        __syncthreads();
        if (tid < NBINS) suf[tid] += add;
        __syncthreads();
    }

    if (tid < NBINS) {
        bool qual = (tid >= NBIN_NEG) ? (suf[tid] >= MAXFG) : (suf[tid] >= KOUT);
        unsigned mask = __ballot_sync(0xFFFFFFFFu, qual);
        if (qual && (mask >> (lane + 1)) == 0) {
            if (tid >= NBIN_NEG) atomicMax(&s_tpos, tid);
            else                 atomicMax(&s_tneg, tid);
        }
    }
    __syncthreads();

    const int tpos = s_tpos, tneg = s_tneg;
    const int pc      = suf[NBIN_NEG];
    const int ppc     = suf[tpos];
    const int negtake = suf[tneg];
    const int nsel    = pc < MAXFG ? pc : MAXFG;
    const int negwin  = KOUT - nsel;
    const int nposb = NBINS - tpos;
    const int nnegb = NBIN_NEG - tneg;
    const int nb_tot = nposb + nnegb;

    if (slice == 0 && tid == 0) {
        g_meta[b * 4 + 0] = pc;
        g_meta[b * 4 + 1] = ppc;
        g_meta[b * 4 + 2] = negtake;
    }

    const int gw = slice * SORT_WARPS + warp;
    for (int i = gw; i < nb_tot; i += SORT_STRIDE) {
        const bool isPos = (i < nposb);
        const int bin = isPos ? (tpos + i) : (tneg + (i - nposb));
        const int cnt = h[bin];
        if (cnt == 0) continue;
        const int r0 = (bin == NBINS - 1 || bin == NBIN_NEG - 1) ? 0 : suf[bin + 1];
        if (isPos ? (r0 >= nsel) : (r0 >= negwin)) continue;
        const int off = isPos ? r0 : (ppc + r0);
        const u64* __restrict__ bk = g_bucket + (size_t)(b * NBINS + bin) * BCAP;
        u64* __restrict__ dst = g_sorted + b * 896 + off;
        if (cnt <= 32) {
            u64 v = (lane < cnt) ? bk[lane] : 0ULL;
            warp_sort32(v);
            if (lane < cnt) dst[lane] = v;
        } else {
            u64 v0 = (2 * lane     < cnt) ? bk[2 * lane]     : 0ULL;
            u64 v1 = (2 * lane + 1 < cnt) ? bk[2 * lane + 1] : 0ULL;
            warp_sort64(v0, v1);
            if (2 * lane     < cnt) dst[2 * lane]     = v0;
            if (2 * lane + 1 < cnt) dst[2 * lane + 1] = v1;
        }
    }
}

// ---------------------------------------------------------------------------
// K2b: emit 512 rows per batch (+ argmax recompute for pos rows), re-zero hist.
// grid = BB x 1024.
// ---------------------------------------------------------------------------
__global__ __launch_bounds__(1024) void k_emit(
    const float4* __restrict__ boxes,
    const float4* __restrict__ gts,
    const int*    __restrict__ labels,
    float*        __restrict__ out)
{
    __shared__ float4 sgt[GG];
    __shared__ float  sga[GG];
    __shared__ int s_meta[3];
    const int b = blockIdx.x;
    const int tid = threadIdx.x;

    if (tid < NBINS) g_hist[b * NBINS + tid] = 0;   // replay determinism
    if (tid < GG) {
        float4 g = gts[b * GG + tid];
        sgt[tid] = g;
        sga[tid] = (g.z - g.x) * (g.w - g.y);
    }
    if (tid < 3) s_meta[tid] = g_meta[b * 4 + tid];
    __syncthreads();

    if (tid < KOUT) {
        const int pc      = s_meta[0];
        const int ppc     = s_meta[1];
        const int negtake = s_meta[2];
        const int nsel = pc < MAXFG ? pc : MAXFG;
        const int j    = tid;
        bool have = (j < nsel) || (j - nsel < negtake);
        const int src  = (j < nsel) ? j : (ppc + (j - nsel));
        u64 key = have ? g_sorted[b * 896 + src] : 0ULL;
        unsigned hi = (unsigned)(key >> 32);
        unsigned m  = 0xFFFFFFFFu - (unsigned)(key & 0xFFFFFFFFu);
        bool posb  = hi >= 0xC0000000u;
        bool valid = (hi >= 0x80000000u) && (m < MM);

        float4 roi = make_float4(0.f, 0.f, 0.f, 0.f);
        if (valid) roi = (m < NN) ? boxes[b * NN + m] : gts[b * GG + (m - NN)];

        float4 bt = make_float4(0.f, 0.f, 0.f, 0.f);
        int cls = 0, p2l = 0;
        if (posb && m < MM) {
            float4 bx = roi;
            float ba = (bx.z - bx.x) * (bx.w - bx.y);
            float bi, bu; int bg = 0;
            {
                float4 gt = sgt[0];
                float ih = fminf(bx.z, gt.z) - fmaxf(bx.x, gt.x);
                float iw = fminf(bx.w, gt.w) - fmaxf(bx.y, gt.y);
                bi = fmaxf(ih, 0.f) * fmaxf(iw, 0.f);
                bu = ba + sga[0] - bi;
            }
            #pragma unroll 4
            for (int g = 1; g < GG; g++) {
                float4 gt = sgt[g];
                float ih = fminf(bx.z, gt.z) - fmaxf(bx.x, gt.x);
                float iw = fminf(bx.w, gt.w) - fmaxf(bx.y, gt.y);
                float ia = fmaxf(ih, 0.f) * fmaxf(iw, 0.f);
                float un = ba + sga[g] - ia;
                if (ia * bu > bi * un) { bi = ia; bu = un; bg = g; }
            }
            bt  = sgt[bg];
            cls = labels[b * GG + bg];
            p2l = bg;
        }

        // out layout: sbox[32,512,4] ++ scls[32,512] ++ rois[32,512,4] ++ sp2l[32,512]
        float4* sbox_o = (float4*)out + b * KOUT + j;
        float*  scls_o = out + BB * KOUT * 4 + b * KOUT + j;
        float4* rois_o = (float4*)(out + BB * KOUT * 4 + BB * KOUT) + b * KOUT + j;
        float*  sp2l_o = out + BB * KOUT * 4 + BB * KOUT + BB * KOUT * 4 + b * KOUT + j;
        *sbox_o = bt;
        *scls_o = (float)cls;
        *rois_o = roi;
        *sp2l_o = (float)p2l;
    }
}

extern "C" void kernel_launch(void* const* d_in, const int* in_sizes, int n_in,
                              void* d_out, int out_size) {
    const float4* boxes  = (const float4*)d_in[0];
    const float4* gts    = (const float4*)d_in[1];
    const int*    labels = (const int*)d_in[2];
    const float*  noise  = (const float*)d_in[3];
    float* out = (float*)d_out;

    k_iou<<<BB * CHUNKS, 128>>>(boxes, gts, noise);
    k_sort<<<dim3(BB, SORT_SLICES), 768>>>();
    k_emit<<<BB, 1024>>>(boxes, gts, labels, out);
}

// round 13
// speedup vs baseline: 1.1923x; 1.1923x over previous
#include <cuda_runtime.h>
#include <cstdint>

// Problem constants
#define BB 32
#define NN 8192
#define GG 128
#define MM 8320            // N + G
#define KOUT 512
#define MAXFG 128

#define NBIN_NEG 512
#define NBIN_POS 256
#define NBINS 768          // neg bins [0,512), pos bins [512,768)
#define BCAP 64            // bucket capacity (expected load ~16)

#define CHUNKS 37          // per-batch chunks in k_iou (32*37 = 1184 = 8*148 blocks)
#define CHUNK 225          // ceil(8320/37); 128 threads x up to 2 boxes

#define SORT_SLICES 8
#define SORT_WARPS 24      // 768 threads
#define SORT_STRIDE (SORT_SLICES * SORT_WARPS)   // 192 warps per batch

typedef unsigned long long u64;

// Scratch (no allocations allowed). g_hist/g_done are zero at load; the last
// k_iou block per batch snapshots hist into g_hist2, zeroes g_hist and resets
// g_done, so every graph replay sees identical initial state.
__device__ int g_hist[BB * NBINS];
__device__ int g_hist2[BB * NBINS];
__device__ int g_done[BB];
__device__ u64 g_bucket[BB * NBINS * BCAP];

__device__ __forceinline__ unsigned int fkey(float f) {
    unsigned int u = __float_as_uint(f);
    return (u & 0x80000000u) ? ~u : (u | 0x80000000u);
}

// Monotone fine binning of the key's high word.
__device__ __forceinline__ int binof(unsigned hi) {
    if (hi < 0x80000000u) return -1;
    float c = __uint_as_float(hi ^ 0x80000000u);
    if (hi >= 0xC0000000u) {
        int t = (int)((c - 2.0f) * (float)NBIN_POS);
        return NBIN_NEG + (t > NBIN_POS - 1 ? NBIN_POS - 1 : t);
    }
    int t = (int)(c * (float)NBIN_NEG);
    return t > NBIN_NEG - 1 ? NBIN_NEG - 1 : t;
}

__device__ __forceinline__ void emit_key(int b, int m, bool pos, bool neg, float nv) {
    float c = pos ? (2.0f + nv) : (neg ? nv : -1.0f);
    unsigned hi = fkey(c);
    u64 key = ((u64)hi << 32) | (u64)(0xFFFFFFFFu - (unsigned)m);
    int bin = binof(hi);
    if (bin >= 0) {
        int slot = atomicAdd(&g_hist[b * NBINS + bin], 1);
        if (slot < BCAP)
            g_bucket[(size_t)(b * NBINS + bin) * BCAP + slot] = key;
    }
}

// ---------------------------------------------------------------------------
// K1: classification only, 2 boxes/thread, one-sided clamp (exactness proven:
// pos/tie outcomes only arise from ih>0 && iw>0 pairs where forms coincide).
// Last block per batch snapshots hist -> hist2 and zeroes hist.
// grid = 1184 blocks x 128 threads (8 blocks/SM exactly).
// ---------------------------------------------------------------------------
__global__ __launch_bounds__(128) void k_iou(
    const float4* __restrict__ boxes,   // [B][N]  (ymin,xmin,ymax,xmax)
    const float4* __restrict__ gts,     // [B][G]
    const float*  __restrict__ noise)   // [B][M]
{
    __shared__ float4 sg[GG];    // {gz, -gx, gw, -gy}
    __shared__ float  snga[GG];  // -ga
    __shared__ int s_last;
    const int b     = blockIdx.x / CHUNKS;
    const int chunk = blockIdx.x % CHUNKS;
    const int tid   = threadIdx.x;

    {
        float4 g = gts[b * GG + tid];
        float ga = (g.z - g.x) * (g.w - g.y);
        sg[tid] = make_float4(g.z, -g.x, g.w, -g.y);
        snga[tid] = -ga;
    }
    __syncthreads();

    const int mstart = chunk * CHUNK;
    const int mend   = (mstart + CHUNK < MM) ? (mstart + CHUNK) : MM;
    const int mA = mstart + tid;
    const int mB = mA + 128;
    const bool vA = mA < mend;
    const bool vB = mB < mend;

    if (vA) {
        float4 bxA = (mA < NN) ? boxes[b * NN + mA] : gts[b * GG + (mA - NN)];
        float4 bxB = vB ? ((mB < NN) ? boxes[b * NN + mB] : gts[b * GG + (mB - NN)]) : bxA;
        float nvA = noise[b * MM + mA];
        float nvB = vB ? noise[b * MM + mB] : 0.0f;
        float baA = (bxA.z - bxA.x) * (bxA.w - bxA.y);
        float baB = (bxB.z - bxB.x) * (bxB.w - bxB.y);

        const float zA = bxA.z, nxA = -bxA.x, wA = bxA.w, nyA = -bxA.y;
        const float zB = bxB.z, nxB = -bxB.x, wB = bxB.w, nyB = -bxB.y;
        float uA = -1e30f, uB = -1e30f;

        #pragma unroll 8
        for (int g = 0; g < GG; g++) {
            float4 G = sg[g];
            float nga = snga[g];
            {
                float ih = fminf(zA, G.x) + fminf(nxA, G.y);
                float iw = fminf(wA, G.z) + fminf(nyA, G.w);
                float ia = fmaxf(ih, 0.f) * iw;          // one-sided clamp
                uA = fmaxf(uA, fmaf(3.0f, ia, nga));
            }
            {
                float ih = fminf(zB, G.x) + fminf(nxB, G.y);
                float iw = fminf(wB, G.z) + fminf(nyB, G.w);
                float ia = fmaxf(ih, 0.f) * iw;
                uB = fmaxf(uB, fmaf(3.0f, ia, nga));
            }
        }

        emit_key(b, mA, uA > baA, uA < baA, nvA);
        if (vB) emit_key(b, mB, uB > baB, uB < baB, nvB);
    }

    // Last-block-per-batch: snapshot hist -> hist2, zero hist for next replay.
    __threadfence();
    __syncthreads();
    if (tid == 0)
        s_last = (atomicAdd(&g_done[b], 1) == CHUNKS - 1) ? 1 : 0;
    __syncthreads();
    if (s_last) {
        for (int i = tid; i < NBINS; i += 128) {
            int v = __ldcg(&g_hist[b * NBINS + i]);
            g_hist2[b * NBINS + i] = v;
            g_hist[b * NBINS + i] = 0;
        }
        if (tid == 0) g_done[b] = 0;
    }
}

// Warp-level bitonic sort, descending, 32 elems (1 per lane).
__device__ __forceinline__ void warp_sort32(u64& v) {
    const int lane = threadIdx.x & 31;
    #pragma unroll
    for (unsigned k = 2; k <= 32; k <<= 1) {
        #pragma unroll
        for (unsigned j = k >> 1; j >= 1; j >>= 1) {
            u64 o = __shfl_xor_sync(0xFFFFFFFFu, v, j);
            bool desc = (lane & k) == 0;
            bool up   = (lane & j) == 0;
            bool keepmax = (up == desc);
            v = keepmax ? (v > o ? v : o) : (v < o ? v : o);
        }
    }
}

// Warp-level bitonic sort, descending, 64 elems (2 per lane: e = 2*lane+s).
__device__ __forceinline__ void warp_sort64(u64& v0, u64& v1) {
    const int lane = threadIdx.x & 31;
    #pragma unroll
    for (unsigned k = 2; k <= 64; k <<= 1) {
        #pragma unroll
        for (unsigned j = k >> 1; j >= 1; j >>= 1) {
            bool desc = (((unsigned)(lane << 1)) & k) == 0;
            if (j == 1) {
                u64 hi2 = v0 > v1 ? v0 : v1;
                u64 lo2 = v0 > v1 ? v1 : v0;
                v0 = desc ? hi2 : lo2;
                v1 = desc ? lo2 : hi2;
            } else {
                unsigned lm = j >> 1;
                u64 o0 = __shfl_xor_sync(0xFFFFFFFFu, v0, lm);
                u64 o1 = __shfl_xor_sync(0xFFFFFFFFu, v1, lm);
                bool up = (lane & lm) == 0;
                bool keepmax = (up == desc);
                v0 = keepmax ? (v0 > o0 ? v0 : o0) : (v0 < o0 ? v0 : o0);
                v1 = keepmax ? (v1 > o1 ? v1 : o1) : (v1 < o1 ? v1 : o1);
            }
        }
    }
}

// Emit one output row j from a sorted key (key always from a valid bucket).
__device__ __forceinline__ void emit_row(
    int b, int j, u64 key,
    const float4* __restrict__ boxes, const float4* __restrict__ gts,
    const int* __restrict__ labels,
    const float4* sgt, const float* sga, float* __restrict__ out)
{
    unsigned hi = (unsigned)(key >> 32);
    unsigned m  = 0xFFFFFFFFu - (unsigned)(key & 0xFFFFFFFFu);
    bool posb = hi >= 0xC0000000u;

    float4 roi = (m < NN) ? boxes[b * NN + m] : gts[b * GG + (m - NN)];
    float4 bt = make_float4(0.f, 0.f, 0.f, 0.f);
    int cls = 0, p2l = 0;
    if (posb) {
        float4 bx = roi;
        float ba = (bx.z - bx.x) * (bx.w - bx.y);
        float bi, bu; int bg = 0;
        {
            float4 gt = sgt[0];
            float ih = fminf(bx.z, gt.z) - fmaxf(bx.x, gt.x);
            float iw = fminf(bx.w, gt.w) - fmaxf(bx.y, gt.y);
            bi = fmaxf(ih, 0.f) * fmaxf(iw, 0.f);
            bu = ba + sga[0] - bi;
        }
        #pragma unroll 4
        for (int g = 1; g < GG; g++) {
            float4 gt = sgt[g];
            float ih = fminf(bx.z, gt.z) - fmaxf(bx.x, gt.x);
            float iw = fminf(bx.w, gt.w) - fmaxf(bx.y, gt.y);
            float ia = fmaxf(ih, 0.f) * fmaxf(iw, 0.f);
            float un = ba + sga[g] - ia;
            if (ia * bu > bi * un) { bi = ia; bu = un; bg = g; }
        }
        bt  = sgt[bg];
        cls = labels[b * GG + bg];
        p2l = bg;
    }

    // out layout: sbox[32,512,4] ++ scls[32,512] ++ rois[32,512,4] ++ sp2l[32,512]
    ((float4*)out)[b * KOUT + j] = bt;
    out[BB * KOUT * 4 + b * KOUT + j] = (float)cls;
    ((float4*)(out + BB * KOUT * 4 + BB * KOUT))[b * KOUT + j] = roi;
    out[BB * KOUT * 4 + BB * KOUT + BB * KOUT * 4 + b * KOUT + j] = (float)p2l;
}

// ---------------------------------------------------------------------------
// K2: fused sort + emit, NO clusters. grid (BB, 8) x 768 threads.
// Each slice reads the hist snapshot, recomputes scan + thresholds, sorts its
// share of the selected buckets in registers and emits rows directly.
// ---------------------------------------------------------------------------
__global__ __launch_bounds__(768) void k_sortemit(
    const float4* __restrict__ boxes,
    const float4* __restrict__ gts,
    const int*    __restrict__ labels,
    float*        __restrict__ out)
{
    __shared__ int h[NBINS];
    __shared__ int suf[NBINS];
    __shared__ float4 sgt[GG];
    __shared__ float  sga[GG];
    __shared__ int s_tpos, s_tneg;
    const int b     = blockIdx.x;
    const int slice = blockIdx.y;
    const int tid   = threadIdx.x;
    const int lane  = tid & 31;
    const int warp  = tid >> 5;

    if (tid < NBINS) {
        int v = g_hist2[b * NBINS + tid];
        if (v > BCAP) v = BCAP;
        h[tid] = v;
        suf[tid] = v;
    }
    if (tid < GG) {
        float4 g = gts[b * GG + tid];
        sgt[tid] = g;
        sga[tid] = (g.z - g.x) * (g.w - g.y);
    }
    if (tid == 0) { s_tpos = NBIN_NEG; s_tneg = 0; }
    __syncthreads();

    // Region-masked suffix scan (neg [0,512), pos [512,768))
    #pragma unroll
    for (int d = 1; d < NBIN_NEG; d <<= 1) {
        int add = 0;
        if (tid < NBINS) {
            int e = (tid < NBIN_NEG) ? NBIN_NEG : NBINS;
            if (tid + d < e) add = suf[tid + d];
        }
        __syncthreads();
        if (tid < NBINS) suf[tid] += add;
        __syncthreads();
    }

    if (tid < NBINS) {
        bool qual = (tid >= NBIN_NEG) ? (suf[tid] >= MAXFG) : (suf[tid] >= KOUT);
        unsigned mask = __ballot_sync(0xFFFFFFFFu, qual);
        if (qual && (mask >> (lane + 1)) == 0) {
            if (tid >= NBIN_NEG) atomicMax(&s_tpos, tid);
            else                 atomicMax(&s_tneg, tid);
        }
    }
    __syncthreads();

    const int tpos = s_tpos, tneg = s_tneg;
    const int pc      = suf[NBIN_NEG];
    const int negtake = suf[tneg];
    const int nsel    = pc < MAXFG ? pc : MAXFG;
    const int negwin  = KOUT - nsel;          // neg ranks [0, negwin) selected
    const int nposb = NBINS - tpos;
    const int nnegb = NBIN_NEG - tneg;
    const int nb_tot = nposb + nnegb;

    const int gw = slice * SORT_WARPS + warp;
    for (int i = gw; i < nb_tot; i += SORT_STRIDE) {
        const bool isPos = (i < nposb);
        const int bin = isPos ? (tpos + i) : (tneg + (i - nposb));
        const int cnt = h[bin];
        if (cnt == 0) continue;
        const int r0 = (bin == NBINS - 1 || bin == NBIN_NEG - 1) ? 0 : suf[bin + 1];
        if (isPos ? (r0 >= nsel) : (r0 >= negwin)) continue;
        const u64* __restrict__ bk = g_bucket + (size_t)(b * NBINS + bin) * BCAP;
        if (cnt <= 32) {
            u64 v = (lane < cnt) ? bk[lane] : 0ULL;
            warp_sort32(v);
            int r = r0 + lane;
            if (lane < cnt) {
                if (isPos) { if (r < nsel) emit_row(b, r, v, boxes, gts, labels, sgt, sga, out); }
                else       { if (r < negwin) emit_row(b, nsel + r, v, boxes, gts, labels, sgt, sga, out); }
            }
        } else {
            u64 v0 = (2 * lane     < cnt) ? bk[2 * lane]     : 0ULL;
            u64 v1 = (2 * lane + 1 < cnt) ? bk[2 * lane + 1] : 0ULL;
            warp_sort64(v0, v1);
            int l0 = 2 * lane, l1 = 2 * lane + 1;
            if (l0 < cnt) {
                int r = r0 + l0;
                if (isPos) { if (r < nsel) emit_row(b, r, v0, boxes, gts, labels, sgt, sga, out); }
                else       { if (r < negwin) emit_row(b, nsel + r, v0, boxes, gts, labels, sgt, sga, out); }
            }
            if (l1 < cnt) {
                int r = r0 + l1;
                if (isPos) { if (r < nsel) emit_row(b, r, v1, boxes, gts, labels, sgt, sga, out); }
                else       { if (r < negwin) emit_row(b, nsel + r, v1, boxes, gts, labels, sgt, sga, out); }
            }
        }
    }

    // Zero-fill any unused tail rows (slice 0 only).
    if (slice == 0) {
        int navail = negtake < negwin ? negtake : negwin;
        int filled = nsel + navail;
        for (int j = filled + tid; j < KOUT; j += 768) {
            ((float4*)out)[b * KOUT + j] = make_float4(0.f, 0.f, 0.f, 0.f);
            out[BB * KOUT * 4 + b * KOUT + j] = 0.f;
            ((float4*)(out + BB * KOUT * 4 + BB * KOUT))[b * KOUT + j] =
                make_float4(0.f, 0.f, 0.f, 0.f);
            out[BB * KOUT * 4 + BB * KOUT + BB * KOUT * 4 + b * KOUT + j] = 0.f;
        }
    }
}

extern "C" void kernel_launch(void* const* d_in, const int* in_sizes, int n_in,
                              void* d_out, int out_size) {
    const float4* boxes  = (const float4*)d_in[0];
    const float4* gts    = (const float4*)d_in[1];
    const int*    labels = (const int*)d_in[2];
    const float*  noise  = (const float*)d_in[3];
    float* out = (float*)d_out;

    k_iou<<<BB * CHUNKS, 128>>>(boxes, gts, noise);
    k_sortemit<<<dim3(BB, SORT_SLICES), 768>>>(boxes, gts, labels, out);
}